// round 13
// baseline (speedup 1.0000x reference)
#include <cuda_runtime.h>
#include <cuda_bf16.h>
#include <cstdint>

#define BB 2
#define TT 4
#define CK 64
#define CV 256
#define HH 64
#define WW 64
#define PH 32
#define PW 32
#define MM 4096
#define NN 4096
#define SCALE2 0.1803368801111204f   // 0.125 * log2(e)  (exp2 domain)
#define KSPLIT 4
#define MSEG (MM / KSPLIT)   // 1024
#define CHM 32               // m per chunk
#define NCH (MSEG / CHM)     // 32 chunks

// Scratch (device globals: allocation-free)
__device__ __align__(128) __nv_bfloat16 g_qk[(size_t)BB * CK * NN];
__device__ __align__(128) __nv_bfloat16 g_mk[(size_t)BB * MM * CK];
__device__ __align__(128) __nv_bfloat16 g_mv[(size_t)BB * CV * MM];
__device__ __align__(128) float g_opart[(size_t)KSPLIT * BB * CV * NN]; // fp32 partial O
__device__ __align__(128) float g_rs[(size_t)KSPLIT * BB * NN];         // partial rowsums
__device__ int g_cnt[BB * 64 * 2];                                      // arrival counters

__device__ __forceinline__ void cpasync16(uint32_t saddr, const void* g) {
    asm volatile("cp.async.cg.shared.global [%0], [%1], 16;" :: "r"(saddr), "l"(g));
}
__device__ __forceinline__ void ldsm4(uint32_t* r, uint32_t a) {
    asm volatile("ldmatrix.sync.aligned.m8n8.x4.shared.b16 {%0,%1,%2,%3},[%4];"
                 : "=r"(r[0]), "=r"(r[1]), "=r"(r[2]), "=r"(r[3]) : "r"(a));
}
__device__ __forceinline__ void ldsm4t(uint32_t* r, uint32_t a) {
    asm volatile("ldmatrix.sync.aligned.m8n8.x4.trans.shared.b16 {%0,%1,%2,%3},[%4];"
                 : "=r"(r[0]), "=r"(r[1]), "=r"(r[2]), "=r"(r[3]) : "r"(a));
}
__device__ __forceinline__ void mma_bf16(float* d, const uint32_t* a, const uint32_t* b) {
    asm volatile(
        "mma.sync.aligned.m16n8k16.row.col.f32.bf16.bf16.f32 "
        "{%0,%1,%2,%3},{%4,%5,%6,%7},{%8,%9},{%0,%1,%2,%3};"
        : "+f"(d[0]), "+f"(d[1]), "+f"(d[2]), "+f"(d[3])
        : "r"(a[0]), "r"(a[1]), "r"(a[2]), "r"(a[3]), "r"(b[0]), "r"(b[1]));
}
__device__ __forceinline__ float ex2(float x) {
    float r;
    asm("ex2.approx.f32 %0, %1;" : "=f"(r) : "f"(x));
    return r;
}
__device__ __forceinline__ uint32_t pack_bf16x2(float a, float b) {
    __nv_bfloat162 h = __floats2bfloat162_rn(a, b);
    return *reinterpret_cast<uint32_t*>(&h);
}

// ---------------- prep: cvtq + counter reset + pools + qv copy ----------------
// blocks [0,512): cvtq (block 0 also zeroes counters)
// [512,1536): pool_k; [1536,5632): pool_v; [5632,7680): qv copy
__global__ void __launch_bounds__(256) prep_kernel(const float* __restrict__ mk_in,
                                                   const float* __restrict__ mv_in,
                                                   const float* __restrict__ q_in,
                                                   const float* __restrict__ qv,
                                                   float* __restrict__ out) {
    int blk = blockIdx.x;
    if (blk < 512) {
        if (blk == 0) g_cnt[threadIdx.x] = 0;    // 256 counters = BB*64*2
        int i = blk * 256 + threadIdx.x;
        float4 v = ((const float4*)q_in)[i];
        __nv_bfloat162* dst = (__nv_bfloat162*)g_qk;
        dst[2 * i]     = __floats2bfloat162_rn(v.x * SCALE2, v.y * SCALE2);
        dst[2 * i + 1] = __floats2bfloat162_rn(v.z * SCALE2, v.w * SCALE2);
    } else if (blk < 1536) {
        int idx = (blk - 512) * 256 + threadIdx.x;     // [0, 262144)
        int pw2 = idx & 15; int t1 = idx >> 4;
        int ph = t1 & 31;   int t2 = t1 >> 5;
        int ck = t2 & 63;   int t3 = t2 >> 6;
        int t  = t3 & 3;    int b  = t3 >> 2;
        const float* base = mk_in + ((((size_t)(b * TT + t) * CK + ck) * HH + ph * 2) * WW + pw2 * 4);
        float4 r0 = *(const float4*)base;
        float4 r1 = *(const float4*)(base + WW);
        float v0 = fmaxf(fmaxf(r0.x, r0.y), fmaxf(r1.x, r1.y));
        float v1 = fmaxf(fmaxf(r0.z, r0.w), fmaxf(r1.z, r1.w));
        int m = t * (PH * PW) + ph * PW + pw2 * 2;
        g_mk[((size_t)b * MM + m) * CK + ck]     = __float2bfloat16_rn(v0);
        g_mk[((size_t)b * MM + m + 1) * CK + ck] = __float2bfloat16_rn(v1);
    } else if (blk < 5632) {
        int idx = (blk - 1536) * 256 + threadIdx.x;    // [0, 1048576)
        int pw2 = idx & 15; int t1 = idx >> 4;
        int ph = t1 & 31;   int t2 = t1 >> 5;
        int c  = t2 & 255;  int t3 = t2 >> 8;
        int t  = t3 & 3;    int b  = t3 >> 2;
        const float* base = mv_in + ((((size_t)(b * TT + t) * CV + c) * HH + ph * 2) * WW + pw2 * 4);
        float4 r0 = *(const float4*)base;
        float4 r1 = *(const float4*)(base + WW);
        float v0 = fmaxf(fmaxf(r0.x, r0.y), fmaxf(r1.x, r1.y));
        float v1 = fmaxf(fmaxf(r0.z, r0.w), fmaxf(r1.z, r1.w));
        int m = t * (PH * PW) + ph * PW + pw2 * 2;
        *(__nv_bfloat162*)(g_mv + ((size_t)b * CV + c) * MM + m) = __floats2bfloat162_rn(v0, v1);
    } else {
        int i = (blk - 5632) * 256 + threadIdx.x;
        const int per_b = CV * NN / 4;
        int b = i / per_b;
        int r = i - b * per_b;
        ((float4*)out)[(size_t)b * (2 * CV * NN / 4) + r] = ((const float4*)qv)[i];
    }
}

// ---------------- fused attention, split-K, 32n x 64c warp tiles, last-CTA combine ----
// CTA: 64n x 128c x 1024m-seg, 4 warps = 2 n-halves x 2 c-halves (warp 32n x 64c).
// grid (8 = 2 chalf * 4 ks, 64 n, 2 b) = 1024 CTAs; 3 CTAs/SM.
// smem: Qs[64ck][144B] (9216) | 3 stages: Ks[32m][144B] (4608) + Vs[128c][80B] (10240)
#define QS_B 9216u
#define KST_B 4608u
#define STG_B 14848u
#define SMEM_TOTAL (QS_B + 3u * STG_B)   // 53760

__global__ void __launch_bounds__(128, 3) fused_attn_kernel(float* __restrict__ out) {
    extern __shared__ char sm[];
    __shared__ float inv_sm[64];
    __shared__ int is_last;
    const uint32_t sb = (uint32_t)__cvta_generic_to_shared(sm);
    const int b = blockIdx.z, n0 = blockIdx.y * 64;
    const int chalf = blockIdx.x & 1;
    const int c0 = chalf * 128;
    const int ks = blockIdx.x >> 1;
    const int mbase = ks * MSEG;
    const int tid = threadIdx.x;

    const __nv_bfloat16* qb = g_qk + (size_t)b * CK * NN;
    const __nv_bfloat16* kb = g_mk + (size_t)b * MM * CK;
    const __nv_bfloat16* vb = g_mv + (size_t)b * CV * MM;

    // Q load: 64 ck-rows x 8 segs of 16B (pitch 144B)
    #pragma unroll
    for (int i = 0; i < 4; i++) {
        int e = tid + i * 128;
        int row = e >> 3, seg = e & 7;
        cpasync16(sb + (uint32_t)(row * 144 + seg * 16),
                  qb + (size_t)row * NN + n0 + seg * 8);
    }
    asm volatile("cp.async.commit_group;" ::: "memory");

    auto pf = [&](int ch) {
        uint32_t kst = sb + QS_B + (uint32_t)(ch % 3) * STG_B;
        uint32_t vst = kst + KST_B;
        #pragma unroll
        for (int i = 0; i < 2; i++) {          // K: 32 rows x 8 segs
            int e = tid + i * 128;
            int row = e >> 3, seg = e & 7;
            cpasync16(kst + (uint32_t)(row * 144 + seg * 16),
                      kb + (size_t)(mbase + ch * CHM + row) * CK + seg * 8);
        }
        #pragma unroll
        for (int i = 0; i < 4; i++) {          // V: 128 rows x 4 segs
            int e = tid + i * 128;
            int row = e >> 2, seg = e & 3;
            cpasync16(vst + (uint32_t)(row * 80 + seg * 16),
                      vb + (size_t)(c0 + row) * MM + mbase + ch * CHM + seg * 8);
        }
        asm volatile("cp.async.commit_group;" ::: "memory");
    };
    pf(0); pf(1);

    const int wid = tid >> 5, lane = tid & 31;
    const int wn = (wid & 1) * 32;             // warp n base (local)
    const int wc = (wid >> 1) * 64;            // warp c base (local)
    const int g = lane >> 2, t = lane & 3;
    const int lr = (lane & 7) + ((lane >> 4) << 3);
    const int lh = (lane >> 3) & 1;

    asm volatile("cp.async.wait_group 2;" ::: "memory");
    __syncthreads();
    // preload Q A-fragments: 32n x 64k -> q[n16][k16]
    uint32_t q[2][4][4];
    #pragma unroll
    for (int i = 0; i < 2; i++)
        #pragma unroll
        for (int kf = 0; kf < 4; kf++)
            ldsm4t(q[i][kf], sb + (uint32_t)((kf * 16 + lr) * 144 + (wn + i * 16 + lh * 8) * 2));

    float acc_o[2][8][4] = {};
    float rs[2][2] = {};

    for (int ch = 0; ch < NCH; ch++) {
        if (ch + 1 < NCH) asm volatile("cp.async.wait_group 1;" ::: "memory");
        else              asm volatile("cp.async.wait_group 0;" ::: "memory");
        __syncthreads();
        if (ch + 2 < NCH) pf(ch + 2);

        uint32_t kst = sb + QS_B + (uint32_t)(ch % 3) * STG_B;
        uint32_t vst = kst + KST_B;

        // ---- S + exp in two 16-m sub-steps (limits live acc_s to 16 regs) ----
        uint32_t p[2][2][4];
        #pragma unroll
        for (int msub = 0; msub < 2; msub++) {
            float acc_s[2][2][4] = {};
            #pragma unroll
            for (int kf = 0; kf < 4; kf++) {
                uint32_t r[4];
                ldsm4(r, kst + (uint32_t)((msub * 16 + lr) * 144 + kf * 32 + lh * 16));
                #pragma unroll
                for (int i = 0; i < 2; i++) {
                    mma_bf16(acc_s[i][0], q[i][kf], r);
                    mma_bf16(acc_s[i][1], q[i][kf], r + 2);
                }
            }
            #pragma unroll
            for (int i = 0; i < 2; i++) {
                float e0 = ex2(acc_s[i][0][0] - 6.f);
                float e1 = ex2(acc_s[i][0][1] - 6.f);
                float e2 = ex2(acc_s[i][0][2] - 6.f);
                float e3 = ex2(acc_s[i][0][3] - 6.f);
                float f0 = ex2(acc_s[i][1][0] - 6.f);
                float f1 = ex2(acc_s[i][1][1] - 6.f);
                float f2 = ex2(acc_s[i][1][2] - 6.f);
                float f3 = ex2(acc_s[i][1][3] - 6.f);
                rs[i][0] += (e0 + e1) + (f0 + f1);
                rs[i][1] += (e2 + e3) + (f2 + f3);
                p[i][msub][0] = pack_bf16x2(e0, e1);
                p[i][msub][1] = pack_bf16x2(e2, e3);
                p[i][msub][2] = pack_bf16x2(f0, f1);
                p[i][msub][3] = pack_bf16x2(f2, f3);
            }
        }

        // ---- O += P V^T : warp 32n x 64c x 32m ----
        #pragma unroll
        for (int jj = 0; jj < 4; jj++) {
            #pragma unroll
            for (int mk = 0; mk < 2; mk++) {
                uint32_t r[4];
                ldsm4(r, vst + (uint32_t)((wc + jj * 16 + lr) * 80 + mk * 32 + lh * 16));
                #pragma unroll
                for (int i = 0; i < 2; i++) {
                    mma_bf16(acc_o[i][2 * jj],     p[i][mk], r);
                    mma_bf16(acc_o[i][2 * jj + 1], p[i][mk], r + 2);
                }
            }
        }
        __syncthreads();
    }

    // ---- partial rowsum (reduce over t) ----
    #pragma unroll
    for (int i = 0; i < 2; i++) {
        #pragma unroll
        for (int h = 0; h < 2; h++) {
            float r = rs[i][h];
            r += __shfl_xor_sync(0xffffffffu, r, 1);
            r += __shfl_xor_sync(0xffffffffu, r, 2);
            rs[i][h] = r;
        }
    }
    if (t == 0) {
        #pragma unroll
        for (int i = 0; i < 2; i++) {
            int n = n0 + wn + i * 16 + g;
            // both c-half CTAs write identical values (same S computation): benign
            g_rs[((size_t)ks * BB + b) * NN + n]     = rs[i][0];
            g_rs[((size_t)ks * BB + b) * NN + n + 8] = rs[i][1];
        }
    }

    // ---- store unnormalized partial O (fp32) ----
    float* op = g_opart + ((size_t)ks * BB + b) * CV * NN;
    #pragma unroll
    for (int i = 0; i < 2; i++) {
        int n = n0 + wn + i * 16 + g;
        #pragma unroll
        for (int ct = 0; ct < 8; ct++) {
            int c = c0 + wc + ct * 8 + 2 * t;
            op[(size_t)c * NN + n]           = acc_o[i][ct][0];
            op[(size_t)(c + 1) * NN + n]     = acc_o[i][ct][1];
            op[(size_t)c * NN + n + 8]       = acc_o[i][ct][2];
            op[(size_t)(c + 1) * NN + n + 8] = acc_o[i][ct][3];
        }
    }

    // ---- last-CTA combine ----
    __threadfence();
    if (tid == 0) {
        int old = atomicAdd(&g_cnt[(b * 64 + blockIdx.y) * 2 + chalf], 1);
        is_last = (old == KSPLIT - 1) ? 1 : 0;
    }
    __syncthreads();
    if (is_last) {
        __threadfence();
        if (tid < 64) {
            float s = 0.f;
            #pragma unroll
            for (int k2 = 0; k2 < KSPLIT; k2++)
                s += g_rs[((size_t)k2 * BB + b) * NN + n0 + tid];
            inv_sm[tid] = 1.f / s;
        }
        __syncthreads();
        for (int idx = tid; idx < 2048; idx += 128) {
            int cc = idx >> 4;           // 0..127 within c-half
            int nf = idx & 15;           // float4 index within 64n
            int c = c0 + cc;
            size_t off = (size_t)c * NN + n0 + nf * 4;
            float4 a = *(const float4*)(g_opart + ((size_t)0 * BB + b) * CV * NN + off);
            #pragma unroll
            for (int k2 = 1; k2 < KSPLIT; k2++) {
                float4 v = *(const float4*)(g_opart + ((size_t)k2 * BB + b) * CV * NN + off);
                a.x += v.x; a.y += v.y; a.z += v.z; a.w += v.w;
            }
            a.x *= inv_sm[nf * 4 + 0];
            a.y *= inv_sm[nf * 4 + 1];
            a.z *= inv_sm[nf * 4 + 2];
            a.w *= inv_sm[nf * 4 + 3];
            *(float4*)(out + ((size_t)b * 2 * CV + CV + c) * NN + n0 + nf * 4) = a;
        }
    }
}

extern "C" void kernel_launch(void* const* d_in, const int* in_sizes, int n_in,
                              void* d_out, int out_size) {
    const float* memory_keys   = (const float*)d_in[0];
    const float* memory_values = (const float*)d_in[1];
    const float* query_key     = (const float*)d_in[2];
    const float* query_value   = (const float*)d_in[3];
    float* out = (float*)d_out;

    cudaFuncSetAttribute(fused_attn_kernel, cudaFuncAttributeMaxDynamicSharedMemorySize,
                         SMEM_TOTAL);

    prep_kernel<<<7680, 256>>>(memory_keys, memory_values, query_key, query_value, out);

    dim3 gf(2 * KSPLIT, NN / 64, BB);   // (8, 64, 2) = 1024 CTAs
    fused_attn_kernel<<<gf, 128, SMEM_TOTAL>>>(out);
}

// round 14
// speedup vs baseline: 1.0631x; 1.0631x over previous
#include <cuda_runtime.h>
#include <cuda_bf16.h>
#include <cstdint>

#define BB 2
#define TT 4
#define CK 64
#define CV 256
#define HH 64
#define WW 64
#define PH 32
#define PW 32
#define MM 4096
#define NN 4096
#define SCALE2 0.1803368801111204f   // 0.125 * log2(e)
#define KSPLIT 4
#define MSEG (MM / KSPLIT)   // 1024
#define CHM 32               // m per chunk
#define NCH (MSEG / CHM)     // 32 chunks

// Scratch (device globals: allocation-free)
__device__ __align__(128) __nv_bfloat16 g_qk[(size_t)BB * CK * NN];
__device__ __align__(128) __nv_bfloat16 g_mk[(size_t)BB * MM * CK];
__device__ __align__(128) __nv_bfloat16 g_mv[(size_t)BB * CV * MM];
__device__ __align__(128) float g_opart[(size_t)KSPLIT * BB * CV * NN]; // fp32 partial O
__device__ __align__(128) float g_rs[(size_t)KSPLIT * BB * NN];         // partial rowsums
__device__ int g_cnt[BB * 64 * 2];                                      // arrival counters

__device__ __forceinline__ void cpasync16(uint32_t saddr, const void* g) {
    asm volatile("cp.async.cg.shared.global [%0], [%1], 16;" :: "r"(saddr), "l"(g));
}
__device__ __forceinline__ void ldsm4(uint32_t* r, uint32_t a) {
    asm volatile("ldmatrix.sync.aligned.m8n8.x4.shared.b16 {%0,%1,%2,%3},[%4];"
                 : "=r"(r[0]), "=r"(r[1]), "=r"(r[2]), "=r"(r[3]) : "r"(a));
}
__device__ __forceinline__ void ldsm4t(uint32_t* r, uint32_t a) {
    asm volatile("ldmatrix.sync.aligned.m8n8.x4.trans.shared.b16 {%0,%1,%2,%3},[%4];"
                 : "=r"(r[0]), "=r"(r[1]), "=r"(r[2]), "=r"(r[3]) : "r"(a));
}
__device__ __forceinline__ void mma_bf16(float* d, const uint32_t* a, const uint32_t* b) {
    asm volatile(
        "mma.sync.aligned.m16n8k16.row.col.f32.bf16.bf16.f32 "
        "{%0,%1,%2,%3},{%4,%5,%6,%7},{%8,%9},{%0,%1,%2,%3};"
        : "+f"(d[0]), "+f"(d[1]), "+f"(d[2]), "+f"(d[3])
        : "r"(a[0]), "r"(a[1]), "r"(a[2]), "r"(a[3]), "r"(b[0]), "r"(b[1]));
}
__device__ __forceinline__ float ex2(float x) {
    float r;
    asm("ex2.approx.f32 %0, %1;" : "=f"(r) : "f"(x));
    return r;
}
__device__ __forceinline__ uint32_t pack_bf16x2(float a, float b) {
    __nv_bfloat162 h = __floats2bfloat162_rn(a, b);
    return *reinterpret_cast<uint32_t*>(&h);
}

// ---------------- prep: cvtq (block 0 zeroes counters) + pools + qv copy ----------------
__global__ void __launch_bounds__(256) prep_kernel(const float* __restrict__ mk_in,
                                                   const float* __restrict__ mv_in,
                                                   const float* __restrict__ q_in,
                                                   const float* __restrict__ qv,
                                                   float* __restrict__ out) {
    int blk = blockIdx.x;
    if (blk < 512) {
        if (blk == 0) g_cnt[threadIdx.x] = 0;    // 256 counters = BB*64*2
        int i = blk * 256 + threadIdx.x;
        float4 v = ((const float4*)q_in)[i];
        __nv_bfloat162* dst = (__nv_bfloat162*)g_qk;
        dst[2 * i]     = __floats2bfloat162_rn(v.x * SCALE2, v.y * SCALE2);
        dst[2 * i + 1] = __floats2bfloat162_rn(v.z * SCALE2, v.w * SCALE2);
    } else if (blk < 1536) {
        int idx = (blk - 512) * 256 + threadIdx.x;     // [0, 262144)
        int pw2 = idx & 15; int t1 = idx >> 4;
        int ph = t1 & 31;   int t2 = t1 >> 5;
        int ck = t2 & 63;   int t3 = t2 >> 6;
        int t  = t3 & 3;    int b  = t3 >> 2;
        const float* base = mk_in + ((((size_t)(b * TT + t) * CK + ck) * HH + ph * 2) * WW + pw2 * 4);
        float4 r0 = *(const float4*)base;
        float4 r1 = *(const float4*)(base + WW);
        float v0 = fmaxf(fmaxf(r0.x, r0.y), fmaxf(r1.x, r1.y));
        float v1 = fmaxf(fmaxf(r0.z, r0.w), fmaxf(r1.z, r1.w));
        int m = t * (PH * PW) + ph * PW + pw2 * 2;
        g_mk[((size_t)b * MM + m) * CK + ck]     = __float2bfloat16_rn(v0);
        g_mk[((size_t)b * MM + m + 1) * CK + ck] = __float2bfloat16_rn(v1);
    } else if (blk < 5632) {
        int idx = (blk - 1536) * 256 + threadIdx.x;    // [0, 1048576)
        int pw2 = idx & 15; int t1 = idx >> 4;
        int ph = t1 & 31;   int t2 = t1 >> 5;
        int c  = t2 & 255;  int t3 = t2 >> 8;
        int t  = t3 & 3;    int b  = t3 >> 2;
        const float* base = mv_in + ((((size_t)(b * TT + t) * CV + c) * HH + ph * 2) * WW + pw2 * 4);
        float4 r0 = *(const float4*)base;
        float4 r1 = *(const float4*)(base + WW);
        float v0 = fmaxf(fmaxf(r0.x, r0.y), fmaxf(r1.x, r1.y));
        float v1 = fmaxf(fmaxf(r0.z, r0.w), fmaxf(r1.z, r1.w));
        int m = t * (PH * PW) + ph * PW + pw2 * 2;
        *(__nv_bfloat162*)(g_mv + ((size_t)b * CV + c) * MM + m) = __floats2bfloat162_rn(v0, v1);
    } else {
        int i = (blk - 5632) * 256 + threadIdx.x;
        const int per_b = CV * NN / 4;
        int b = i / per_b;
        int r = i - b * per_b;
        ((float4*)out)[(size_t)b * (2 * CV * NN / 4) + r] = ((const float4*)qv)[i];
    }
}

// ---------------- fused attention (R11 tiling), split-K, last-CTA combine ----------------
// CTA: 64n x 128c x 1024m-seg, 4 warps (16n x 128c each; S computed once per CTA).
// grid (8 = 2 chalf * 4 ks, 64 n, 2 b) = 1024 CTAs; target 4 CTAs/SM.
// smem: Qs[64ck][144B] (9216) | 3 stages: Ks[32m][144B] (4608) + Vs[128c][80B] (10240)
#define QS_B 9216u
#define KST_B 4608u
#define STG_B 14848u
#define SMEM_TOTAL (QS_B + 3u * STG_B)   // 53760

__global__ void __launch_bounds__(128, 4) fused_attn_kernel(float* __restrict__ out) {
    extern __shared__ char sm[];
    __shared__ float inv_sm[64];
    __shared__ int is_last;
    const uint32_t sb = (uint32_t)__cvta_generic_to_shared(sm);
    const int b = blockIdx.z, n0 = blockIdx.y * 64;
    const int chalf = blockIdx.x & 1;
    const int c0 = chalf * 128;
    const int ks = blockIdx.x >> 1;
    const int mbase = ks * MSEG;
    const int tid = threadIdx.x;

    const __nv_bfloat16* qb = g_qk + (size_t)b * CK * NN;
    const __nv_bfloat16* kb = g_mk + (size_t)b * MM * CK;
    const __nv_bfloat16* vb = g_mv + (size_t)b * CV * MM;

    // Q load: 64 ck-rows x 8 segs of 16B (pitch 144B)
    #pragma unroll
    for (int i = 0; i < 4; i++) {
        int e = tid + i * 128;
        int row = e >> 3, seg = e & 7;
        cpasync16(sb + (uint32_t)(row * 144 + seg * 16),
                  qb + (size_t)row * NN + n0 + seg * 8);
    }
    asm volatile("cp.async.commit_group;" ::: "memory");

    auto pf = [&](int ch) {
        uint32_t kst = sb + QS_B + (uint32_t)(ch % 3) * STG_B;
        uint32_t vst = kst + KST_B;
        #pragma unroll
        for (int i = 0; i < 2; i++) {          // K: 32 rows x 8 segs
            int e = tid + i * 128;
            int row = e >> 3, seg = e & 7;
            cpasync16(kst + (uint32_t)(row * 144 + seg * 16),
                      kb + (size_t)(mbase + ch * CHM + row) * CK + seg * 8);
        }
        #pragma unroll
        for (int i = 0; i < 4; i++) {          // V: 128 rows x 4 segs
            int e = tid + i * 128;
            int row = e >> 2, seg = e & 3;
            cpasync16(vst + (uint32_t)(row * 80 + seg * 16),
                      vb + (size_t)(c0 + row) * MM + mbase + ch * CHM + seg * 8);
        }
        asm volatile("cp.async.commit_group;" ::: "memory");
    };
    pf(0); pf(1);

    const int wid = tid >> 5, lane = tid & 31;
    const int wn = wid * 16;                   // warp's n base (local)
    const int g = lane >> 2, t = lane & 3;
    const int lr = (lane & 7) + ((lane >> 4) << 3);
    const int lh = (lane >> 3) & 1;

    asm volatile("cp.async.wait_group 2;" ::: "memory");
    __syncthreads();
    uint32_t q[4][4];
    #pragma unroll
    for (int kf = 0; kf < 4; kf++)
        ldsm4t(q[kf], sb + (uint32_t)((kf * 16 + lr) * 144 + (wn + lh * 8) * 2));

    float acc_o[16][4] = {};
    float rs0 = 0.f, rs1 = 0.f;

    for (int ch = 0; ch < NCH; ch++) {
        if (ch + 1 < NCH) asm volatile("cp.async.wait_group 1;" ::: "memory");
        else              asm volatile("cp.async.wait_group 0;" ::: "memory");
        __syncthreads();
        if (ch + 2 < NCH) pf(ch + 2);

        uint32_t kst = sb + QS_B + (uint32_t)(ch % 3) * STG_B;
        uint32_t vst = kst + KST_B;

        // ---- S = Q K^T : warp tile 16n x 32m ----
        float acc_s[4][4] = {};
        #pragma unroll
        for (int jj = 0; jj < 2; jj++)
            #pragma unroll
            for (int kf = 0; kf < 4; kf++) {
                uint32_t r[4];
                ldsm4(r, kst + (uint32_t)((jj * 16 + lr) * 144 + kf * 32 + lh * 16));
                mma_bf16(acc_s[2 * jj],     q[kf], r);
                mma_bf16(acc_s[2 * jj + 1], q[kf], r + 2);
            }

        // ---- exp2 -> P fragments + rowsum ----
        uint32_t p[2][4];
        #pragma unroll
        for (int mk = 0; mk < 2; mk++) {
            float e0 = ex2(acc_s[2 * mk][0] - 6.f);
            float e1 = ex2(acc_s[2 * mk][1] - 6.f);
            float e2 = ex2(acc_s[2 * mk][2] - 6.f);
            float e3 = ex2(acc_s[2 * mk][3] - 6.f);
            float f0 = ex2(acc_s[2 * mk + 1][0] - 6.f);
            float f1 = ex2(acc_s[2 * mk + 1][1] - 6.f);
            float f2 = ex2(acc_s[2 * mk + 1][2] - 6.f);
            float f3 = ex2(acc_s[2 * mk + 1][3] - 6.f);
            rs0 += (e0 + e1) + (f0 + f1);
            rs1 += (e2 + e3) + (f2 + f3);
            p[mk][0] = pack_bf16x2(e0, e1);
            p[mk][1] = pack_bf16x2(e2, e3);
            p[mk][2] = pack_bf16x2(f0, f1);
            p[mk][3] = pack_bf16x2(f2, f3);
        }

        // ---- O += P V^T : warp tile 16n x 128c x 32m ----
        #pragma unroll
        for (int jj = 0; jj < 8; jj++)
            #pragma unroll
            for (int mk = 0; mk < 2; mk++) {
                uint32_t r[4];
                ldsm4(r, vst + (uint32_t)((jj * 16 + lr) * 80 + mk * 32 + lh * 16));
                mma_bf16(acc_o[2 * jj],     p[mk], r);
                mma_bf16(acc_o[2 * jj + 1], p[mk], r + 2);
            }
        __syncthreads();
    }

    // ---- partial rowsum (reduce over t; rows warp-private) ----
    rs0 += __shfl_xor_sync(0xffffffffu, rs0, 1);
    rs0 += __shfl_xor_sync(0xffffffffu, rs0, 2);
    rs1 += __shfl_xor_sync(0xffffffffu, rs1, 1);
    rs1 += __shfl_xor_sync(0xffffffffu, rs1, 2);
    int n = n0 + wn + g;
    if (t == 0) {
        // both c-half CTAs write identical values: benign
        g_rs[((size_t)ks * BB + b) * NN + n]     = rs0;
        g_rs[((size_t)ks * BB + b) * NN + n + 8] = rs1;
    }

    // ---- store unnormalized partial O (fp32) ----
    float* op = g_opart + ((size_t)ks * BB + b) * CV * NN;
    #pragma unroll
    for (int ct = 0; ct < 16; ct++) {
        int c = c0 + ct * 8 + 2 * t;
        op[(size_t)c * NN + n]           = acc_o[ct][0];
        op[(size_t)(c + 1) * NN + n]     = acc_o[ct][1];
        op[(size_t)c * NN + n + 8]       = acc_o[ct][2];
        op[(size_t)(c + 1) * NN + n + 8] = acc_o[ct][3];
    }

    // ---- last-CTA combine for this (b, ntile, chalf) ----
    __threadfence();
    if (tid == 0) {
        int old = atomicAdd(&g_cnt[(b * 64 + blockIdx.y) * 2 + chalf], 1);
        is_last = (old == KSPLIT - 1) ? 1 : 0;
    }
    __syncthreads();
    if (is_last) {
        __threadfence();
        if (tid < 64) {
            float s = 0.f;
            #pragma unroll
            for (int k2 = 0; k2 < KSPLIT; k2++)
                s += g_rs[((size_t)k2 * BB + b) * NN + n0 + tid];
            inv_sm[tid] = 1.f / s;
        }
        __syncthreads();
        for (int idx = tid; idx < 2048; idx += 128) {
            int cc = idx >> 4;           // 0..127 within c-half
            int nf = idx & 15;           // float4 index within 64n
            int c = c0 + cc;
            size_t off = (size_t)c * NN + n0 + nf * 4;
            float4 a = *(const float4*)(g_opart + ((size_t)0 * BB + b) * CV * NN + off);
            #pragma unroll
            for (int k2 = 1; k2 < KSPLIT; k2++) {
                float4 v = *(const float4*)(g_opart + ((size_t)k2 * BB + b) * CV * NN + off);
                a.x += v.x; a.y += v.y; a.z += v.z; a.w += v.w;
            }
            a.x *= inv_sm[nf * 4 + 0];
            a.y *= inv_sm[nf * 4 + 1];
            a.z *= inv_sm[nf * 4 + 2];
            a.w *= inv_sm[nf * 4 + 3];
            *(float4*)(out + ((size_t)b * 2 * CV + CV + c) * NN + n0 + nf * 4) = a;
        }
    }
}

extern "C" void kernel_launch(void* const* d_in, const int* in_sizes, int n_in,
                              void* d_out, int out_size) {
    const float* memory_keys   = (const float*)d_in[0];
    const float* memory_values = (const float*)d_in[1];
    const float* query_key     = (const float*)d_in[2];
    const float* query_value   = (const float*)d_in[3];
    float* out = (float*)d_out;

    cudaFuncSetAttribute(fused_attn_kernel, cudaFuncAttributeMaxDynamicSharedMemorySize,
                         SMEM_TOTAL);

    prep_kernel<<<7680, 256>>>(memory_keys, memory_values, query_key, query_value, out);

    dim3 gf(2 * KSPLIT, NN / 64, BB);   // (8, 64, 2) = 1024 CTAs
    fused_attn_kernel<<<gf, 128, SMEM_TOTAL>>>(out);
}

// round 15
// speedup vs baseline: 1.0937x; 1.0287x over previous
#include <cuda_runtime.h>
#include <cuda_bf16.h>
#include <cstdint>

#define BB 2
#define TT 4
#define CK 64
#define CV 256
#define HH 64
#define WW 64
#define PH 32
#define PW 32
#define MM 4096
#define NN 4096
#define SCALE2 0.1803368801111204f   // 0.125 * log2(e)
#define KSPLIT 4
#define MSEG (MM / KSPLIT)   // 1024
#define CHM 32               // m per chunk
#define NCH (MSEG / CHM)     // 32 chunks

// Scratch (device globals: allocation-free)
__device__ __align__(128) __nv_bfloat16 g_qk[(size_t)BB * CK * NN];
__device__ __align__(128) __nv_bfloat16 g_mk[(size_t)BB * MM * CK];
__device__ __align__(128) __nv_bfloat16 g_mv[(size_t)BB * CV * MM];
__device__ __align__(128) float g_opart[(size_t)KSPLIT * BB * CV * NN]; // fp32 partial O
__device__ __align__(128) float g_rs[(size_t)KSPLIT * BB * NN];         // partial rowsums
__device__ int g_cnt[BB * 64 * 2];                                      // arrival counters

__device__ __forceinline__ void cpasync16(uint32_t saddr, const void* g) {
    asm volatile("cp.async.cg.shared.global [%0], [%1], 16;" :: "r"(saddr), "l"(g));
}
__device__ __forceinline__ void ldsm4(uint32_t* r, uint32_t a) {
    asm volatile("ldmatrix.sync.aligned.m8n8.x4.shared.b16 {%0,%1,%2,%3},[%4];"
                 : "=r"(r[0]), "=r"(r[1]), "=r"(r[2]), "=r"(r[3]) : "r"(a));
}
__device__ __forceinline__ void ldsm4t(uint32_t* r, uint32_t a) {
    asm volatile("ldmatrix.sync.aligned.m8n8.x4.trans.shared.b16 {%0,%1,%2,%3},[%4];"
                 : "=r"(r[0]), "=r"(r[1]), "=r"(r[2]), "=r"(r[3]) : "r"(a));
}
__device__ __forceinline__ void mma_bf16(float* d, const uint32_t* a, const uint32_t* b) {
    asm volatile(
        "mma.sync.aligned.m16n8k16.row.col.f32.bf16.bf16.f32 "
        "{%0,%1,%2,%3},{%4,%5,%6,%7},{%8,%9},{%0,%1,%2,%3};"
        : "+f"(d[0]), "+f"(d[1]), "+f"(d[2]), "+f"(d[3])
        : "r"(a[0]), "r"(a[1]), "r"(a[2]), "r"(a[3]), "r"(b[0]), "r"(b[1]));
}
__device__ __forceinline__ float ex2(float x) {
    float r;
    asm("ex2.approx.f32 %0, %1;" : "=f"(r) : "f"(x));
    return r;
}
__device__ __forceinline__ uint32_t pack_bf16x2(float a, float b) {
    __nv_bfloat162 h = __floats2bfloat162_rn(a, b);
    return *reinterpret_cast<uint32_t*>(&h);
}

// ---------------- prep: cvtq (block 0 zeroes counters) + pools + qv copy ----------------
__global__ void __launch_bounds__(256) prep_kernel(const float* __restrict__ mk_in,
                                                   const float* __restrict__ mv_in,
                                                   const float* __restrict__ q_in,
                                                   const float* __restrict__ qv,
                                                   float* __restrict__ out) {
    int blk = blockIdx.x;
    if (blk < 512) {
        if (blk == 0) g_cnt[threadIdx.x] = 0;    // 256 counters = BB*64*2
        int i = blk * 256 + threadIdx.x;
        float4 v = ((const float4*)q_in)[i];
        __nv_bfloat162* dst = (__nv_bfloat162*)g_qk;
        dst[2 * i]     = __floats2bfloat162_rn(v.x * SCALE2, v.y * SCALE2);
        dst[2 * i + 1] = __floats2bfloat162_rn(v.z * SCALE2, v.w * SCALE2);
    } else if (blk < 1536) {
        int idx = (blk - 512) * 256 + threadIdx.x;     // [0, 262144)
        int pw2 = idx & 15; int t1 = idx >> 4;
        int ph = t1 & 31;   int t2 = t1 >> 5;
        int ck = t2 & 63;   int t3 = t2 >> 6;
        int t  = t3 & 3;    int b  = t3 >> 2;
        const float* base = mk_in + ((((size_t)(b * TT + t) * CK + ck) * HH + ph * 2) * WW + pw2 * 4);
        float4 r0 = *(const float4*)base;
        float4 r1 = *(const float4*)(base + WW);
        float v0 = fmaxf(fmaxf(r0.x, r0.y), fmaxf(r1.x, r1.y));
        float v1 = fmaxf(fmaxf(r0.z, r0.w), fmaxf(r1.z, r1.w));
        int m = t * (PH * PW) + ph * PW + pw2 * 2;
        g_mk[((size_t)b * MM + m) * CK + ck]     = __float2bfloat16_rn(v0);
        g_mk[((size_t)b * MM + m + 1) * CK + ck] = __float2bfloat16_rn(v1);
    } else if (blk < 5632) {
        int idx = (blk - 1536) * 256 + threadIdx.x;    // [0, 1048576)
        int pw2 = idx & 15; int t1 = idx >> 4;
        int ph = t1 & 31;   int t2 = t1 >> 5;
        int c  = t2 & 255;  int t3 = t2 >> 8;
        int t  = t3 & 3;    int b  = t3 >> 2;
        const float* base = mv_in + ((((size_t)(b * TT + t) * CV + c) * HH + ph * 2) * WW + pw2 * 4);
        float4 r0 = *(const float4*)base;
        float4 r1 = *(const float4*)(base + WW);
        float v0 = fmaxf(fmaxf(r0.x, r0.y), fmaxf(r1.x, r1.y));
        float v1 = fmaxf(fmaxf(r0.z, r0.w), fmaxf(r1.z, r1.w));
        int m = t * (PH * PW) + ph * PW + pw2 * 2;
        *(__nv_bfloat162*)(g_mv + ((size_t)b * CV + c) * MM + m) = __floats2bfloat162_rn(v0, v1);
    } else {
        int i = (blk - 5632) * 256 + threadIdx.x;
        const int per_b = CV * NN / 4;
        int b = i / per_b;
        int r = i - b * per_b;
        ((float4*)out)[(size_t)b * (2 * CV * NN / 4) + r] = ((const float4*)qv)[i];
    }
}

// ---------------- fused attention (R11 tiling), split-K, last-CTA combine ----------------
// CTA: 64n x 128c x 1024m-seg, 4 warps (16n x 128c each; S computed once per CTA).
// grid (8 = 2 chalf * 4 ks, 64 n, 2 b) = 1024 CTAs; 3 CTAs/SM (no reg spill).
// smem: Qs[64ck][144B] (9216) | 3 stages: Ks[32m][144B] (4608) + Vs[128c][80B] (10240)
#define QS_B 9216u
#define KST_B 4608u
#define STG_B 14848u
#define SMEM_TOTAL (QS_B + 3u * STG_B)   // 53760

__global__ void __launch_bounds__(128, 3) fused_attn_kernel(float* __restrict__ out) {
    extern __shared__ char sm[];
    __shared__ float inv_sm[64];
    __shared__ int is_last;
    const uint32_t sb = (uint32_t)__cvta_generic_to_shared(sm);
    const int b = blockIdx.z, n0 = blockIdx.y * 64;
    const int chalf = blockIdx.x & 1;
    const int c0 = chalf * 128;
    const int ks = blockIdx.x >> 1;
    const int mbase = ks * MSEG;
    const int tid = threadIdx.x;

    const __nv_bfloat16* qb = g_qk + (size_t)b * CK * NN;
    const __nv_bfloat16* kb = g_mk + (size_t)b * MM * CK;
    const __nv_bfloat16* vb = g_mv + (size_t)b * CV * MM;

    // Q load: 64 ck-rows x 8 segs of 16B (pitch 144B)
    #pragma unroll
    for (int i = 0; i < 4; i++) {
        int e = tid + i * 128;
        int row = e >> 3, seg = e & 7;
        cpasync16(sb + (uint32_t)(row * 144 + seg * 16),
                  qb + (size_t)row * NN + n0 + seg * 8);
    }
    asm volatile("cp.async.commit_group;" ::: "memory");

    auto pf = [&](int ch) {
        uint32_t kst = sb + QS_B + (uint32_t)(ch % 3) * STG_B;
        uint32_t vst = kst + KST_B;
        #pragma unroll
        for (int i = 0; i < 2; i++) {          // K: 32 rows x 8 segs
            int e = tid + i * 128;
            int row = e >> 3, seg = e & 7;
            cpasync16(kst + (uint32_t)(row * 144 + seg * 16),
                      kb + (size_t)(mbase + ch * CHM + row) * CK + seg * 8);
        }
        #pragma unroll
        for (int i = 0; i < 4; i++) {          // V: 128 rows x 4 segs
            int e = tid + i * 128;
            int row = e >> 2, seg = e & 3;
            cpasync16(vst + (uint32_t)(row * 80 + seg * 16),
                      vb + (size_t)(c0 + row) * MM + mbase + ch * CHM + seg * 8);
        }
        asm volatile("cp.async.commit_group;" ::: "memory");
    };
    pf(0); pf(1);

    const int wid = tid >> 5, lane = tid & 31;
    const int wn = wid * 16;                   // warp's n base (local)
    const int g = lane >> 2, t = lane & 3;
    const int lr = (lane & 7) + ((lane >> 4) << 3);
    const int lh = (lane >> 3) & 1;

    asm volatile("cp.async.wait_group 2;" ::: "memory");
    __syncthreads();
    uint32_t q[4][4];
    #pragma unroll
    for (int kf = 0; kf < 4; kf++)
        ldsm4t(q[kf], sb + (uint32_t)((kf * 16 + lr) * 144 + (wn + lh * 8) * 2));

    float acc_o[16][4] = {};
    float rs0 = 0.f, rs1 = 0.f;

    for (int ch = 0; ch < NCH; ch++) {
        if (ch + 1 < NCH) asm volatile("cp.async.wait_group 1;" ::: "memory");
        else              asm volatile("cp.async.wait_group 0;" ::: "memory");
        __syncthreads();
        if (ch + 2 < NCH) pf(ch + 2);

        uint32_t kst = sb + QS_B + (uint32_t)(ch % 3) * STG_B;
        uint32_t vst = kst + KST_B;

        // ---- S = Q K^T : warp tile 16n x 32m ----
        float acc_s[4][4] = {};
        #pragma unroll
        for (int jj = 0; jj < 2; jj++)
            #pragma unroll
            for (int kf = 0; kf < 4; kf++) {
                uint32_t r[4];
                ldsm4(r, kst + (uint32_t)((jj * 16 + lr) * 144 + kf * 32 + lh * 16));
                mma_bf16(acc_s[2 * jj],     q[kf], r);
                mma_bf16(acc_s[2 * jj + 1], q[kf], r + 2);
            }

        // ---- exp2 -> P fragments + rowsum ----
        uint32_t p[2][4];
        #pragma unroll
        for (int mk = 0; mk < 2; mk++) {
            float e0 = ex2(acc_s[2 * mk][0] - 6.f);
            float e1 = ex2(acc_s[2 * mk][1] - 6.f);
            float e2 = ex2(acc_s[2 * mk][2] - 6.f);
            float e3 = ex2(acc_s[2 * mk][3] - 6.f);
            float f0 = ex2(acc_s[2 * mk + 1][0] - 6.f);
            float f1 = ex2(acc_s[2 * mk + 1][1] - 6.f);
            float f2 = ex2(acc_s[2 * mk + 1][2] - 6.f);
            float f3 = ex2(acc_s[2 * mk + 1][3] - 6.f);
            rs0 += (e0 + e1) + (f0 + f1);
            rs1 += (e2 + e3) + (f2 + f3);
            p[mk][0] = pack_bf16x2(e0, e1);
            p[mk][1] = pack_bf16x2(e2, e3);
            p[mk][2] = pack_bf16x2(f0, f1);
            p[mk][3] = pack_bf16x2(f2, f3);
        }

        // ---- O += P V^T : warp tile 16n x 128c x 32m ----
        #pragma unroll
        for (int jj = 0; jj < 8; jj++)
            #pragma unroll
            for (int mk = 0; mk < 2; mk++) {
                uint32_t r[4];
                ldsm4(r, vst + (uint32_t)((jj * 16 + lr) * 80 + mk * 32 + lh * 16));
                mma_bf16(acc_o[2 * jj],     p[mk], r);
                mma_bf16(acc_o[2 * jj + 1], p[mk], r + 2);
            }
        __syncthreads();
    }

    // ---- partial rowsum (reduce over t; rows warp-private) ----
    rs0 += __shfl_xor_sync(0xffffffffu, rs0, 1);
    rs0 += __shfl_xor_sync(0xffffffffu, rs0, 2);
    rs1 += __shfl_xor_sync(0xffffffffu, rs1, 1);
    rs1 += __shfl_xor_sync(0xffffffffu, rs1, 2);
    int n = n0 + wn + g;
    if (t == 0) {
        // both c-half CTAs write identical values: benign
        g_rs[((size_t)ks * BB + b) * NN + n]     = rs0;
        g_rs[((size_t)ks * BB + b) * NN + n + 8] = rs1;
    }

    // ---- store unnormalized partial O (fp32) ----
    float* op = g_opart + ((size_t)ks * BB + b) * CV * NN;
    #pragma unroll
    for (int ct = 0; ct < 16; ct++) {
        int c = c0 + ct * 8 + 2 * t;
        op[(size_t)c * NN + n]           = acc_o[ct][0];
        op[(size_t)(c + 1) * NN + n]     = acc_o[ct][1];
        op[(size_t)c * NN + n + 8]       = acc_o[ct][2];
        op[(size_t)(c + 1) * NN + n + 8] = acc_o[ct][3];
    }

    // ---- last-CTA combine for this (b, ntile, chalf) ----
    __threadfence();
    if (tid == 0) {
        int old = atomicAdd(&g_cnt[(b * 64 + blockIdx.y) * 2 + chalf], 1);
        is_last = (old == KSPLIT - 1) ? 1 : 0;
    }
    __syncthreads();
    if (is_last) {
        __threadfence();
        if (tid < 64) {
            float s = 0.f;
            #pragma unroll
            for (int k2 = 0; k2 < KSPLIT; k2++)
                s += g_rs[((size_t)k2 * BB + b) * NN + n0 + tid];
            inv_sm[tid] = 1.f / s;
        }
        __syncthreads();
        for (int idx = tid; idx < 2048; idx += 128) {
            int cc = idx >> 4;           // 0..127 within c-half
            int nf = idx & 15;           // float4 index within 64n
            int c = c0 + cc;
            size_t off = (size_t)c * NN + n0 + nf * 4;
            float4 a = *(const float4*)(g_opart + ((size_t)0 * BB + b) * CV * NN + off);
            #pragma unroll
            for (int k2 = 1; k2 < KSPLIT; k2++) {
                float4 v = *(const float4*)(g_opart + ((size_t)k2 * BB + b) * CV * NN + off);
                a.x += v.x; a.y += v.y; a.z += v.z; a.w += v.w;
            }
            a.x *= inv_sm[nf * 4 + 0];
            a.y *= inv_sm[nf * 4 + 1];
            a.z *= inv_sm[nf * 4 + 2];
            a.w *= inv_sm[nf * 4 + 3];
            *(float4*)(out + ((size_t)b * 2 * CV + CV + c) * NN + n0 + nf * 4) = a;
        }
    }
}

extern "C" void kernel_launch(void* const* d_in, const int* in_sizes, int n_in,
                              void* d_out, int out_size) {
    const float* memory_keys   = (const float*)d_in[0];
    const float* memory_values = (const float*)d_in[1];
    const float* query_key     = (const float*)d_in[2];
    const float* query_value   = (const float*)d_in[3];
    float* out = (float*)d_out;

    cudaFuncSetAttribute(fused_attn_kernel, cudaFuncAttributeMaxDynamicSharedMemorySize,
                         SMEM_TOTAL);

    prep_kernel<<<7680, 256>>>(memory_keys, memory_values, query_key, query_value, out);

    dim3 gf(2 * KSPLIT, NN / 64, BB);   // (8, 64, 2) = 1024 CTAs
    fused_attn_kernel<<<gf, 128, SMEM_TOTAL>>>(out);
}

// round 16
// speedup vs baseline: 1.3198x; 1.2067x over previous
#include <cuda_runtime.h>
#include <cuda_bf16.h>
#include <cstdint>

#define BB 2
#define TT 4
#define CK 64
#define CV 256
#define HH 64
#define WW 64
#define PH 32
#define PW 32
#define MM 4096
#define NN 4096
#define SCALE2 0.1803368801111204f   // 0.125 * log2(e)

// Scratch (device globals: allocation-free)
__device__ __align__(128) __nv_bfloat16 g_qk[(size_t)BB * CK * NN];   // scaled Q (exp2 domain)
__device__ __align__(128) __nv_bfloat16 g_mk[(size_t)BB * MM * CK];   // pooled K
__device__ __align__(128) __nv_bfloat16 g_mv[(size_t)BB * CV * MM];   // pooled V [b][c][m]

__device__ __forceinline__ void cpasync16(uint32_t saddr, const void* g) {
    asm volatile("cp.async.cg.shared.global [%0], [%1], 16;" :: "r"(saddr), "l"(g));
}
__device__ __forceinline__ void ldsm4(uint32_t* r, uint32_t a) {
    asm volatile("ldmatrix.sync.aligned.m8n8.x4.shared.b16 {%0,%1,%2,%3},[%4];"
                 : "=r"(r[0]), "=r"(r[1]), "=r"(r[2]), "=r"(r[3]) : "r"(a));
}
__device__ __forceinline__ void ldsm4t(uint32_t* r, uint32_t a) {
    asm volatile("ldmatrix.sync.aligned.m8n8.x4.trans.shared.b16 {%0,%1,%2,%3},[%4];"
                 : "=r"(r[0]), "=r"(r[1]), "=r"(r[2]), "=r"(r[3]) : "r"(a));
}
__device__ __forceinline__ void mma_bf16(float* d, const uint32_t* a, const uint32_t* b) {
    asm volatile(
        "mma.sync.aligned.m16n8k16.row.col.f32.bf16.bf16.f32 "
        "{%0,%1,%2,%3},{%4,%5,%6,%7},{%8,%9},{%0,%1,%2,%3};"
        : "+f"(d[0]), "+f"(d[1]), "+f"(d[2]), "+f"(d[3])
        : "r"(a[0]), "r"(a[1]), "r"(a[2]), "r"(a[3]), "r"(b[0]), "r"(b[1]));
}
__device__ __forceinline__ float ex2(float x) {
    float r;
    asm("ex2.approx.f32 %0, %1;" : "=f"(r) : "f"(x));
    return r;
}
__device__ __forceinline__ uint32_t pack_bf16x2(float a, float b) {
    __nv_bfloat162 h = __floats2bfloat162_rn(a, b);
    return *reinterpret_cast<uint32_t*>(&h);
}

// ---------------- fused prep: cvtq + pool_k + pool_v + qv copy (single launch) ----------
// blocks [0,512): cvtq; [512,1536): pool_k; [1536,5632): pool_v; [5632,7680): qv copy
__global__ void __launch_bounds__(256) prep_kernel(const float* __restrict__ mk_in,
                                                   const float* __restrict__ mv_in,
                                                   const float* __restrict__ q_in,
                                                   const float* __restrict__ qv,
                                                   float* __restrict__ out) {
    int blk = blockIdx.x;
    if (blk < 512) {
        int i = blk * 256 + threadIdx.x;
        float4 v = ((const float4*)q_in)[i];
        __nv_bfloat162* dst = (__nv_bfloat162*)g_qk;
        dst[2 * i]     = __floats2bfloat162_rn(v.x * SCALE2, v.y * SCALE2);
        dst[2 * i + 1] = __floats2bfloat162_rn(v.z * SCALE2, v.w * SCALE2);
    } else if (blk < 1536) {
        int idx = (blk - 512) * 256 + threadIdx.x;     // [0, 262144)
        int pw2 = idx & 15; int t1 = idx >> 4;
        int ph = t1 & 31;   int t2 = t1 >> 5;
        int ck = t2 & 63;   int t3 = t2 >> 6;
        int t  = t3 & 3;    int b  = t3 >> 2;
        const float* base = mk_in + ((((size_t)(b * TT + t) * CK + ck) * HH + ph * 2) * WW + pw2 * 4);
        float4 r0 = *(const float4*)base;
        float4 r1 = *(const float4*)(base + WW);
        float v0 = fmaxf(fmaxf(r0.x, r0.y), fmaxf(r1.x, r1.y));
        float v1 = fmaxf(fmaxf(r0.z, r0.w), fmaxf(r1.z, r1.w));
        int m = t * (PH * PW) + ph * PW + pw2 * 2;
        g_mk[((size_t)b * MM + m) * CK + ck]     = __float2bfloat16_rn(v0);
        g_mk[((size_t)b * MM + m + 1) * CK + ck] = __float2bfloat16_rn(v1);
    } else if (blk < 5632) {
        int idx = (blk - 1536) * 256 + threadIdx.x;    // [0, 1048576)
        int pw2 = idx & 15; int t1 = idx >> 4;
        int ph = t1 & 31;   int t2 = t1 >> 5;
        int c  = t2 & 255;  int t3 = t2 >> 8;
        int t  = t3 & 3;    int b  = t3 >> 2;
        const float* base = mv_in + ((((size_t)(b * TT + t) * CV + c) * HH + ph * 2) * WW + pw2 * 4);
        float4 r0 = *(const float4*)base;
        float4 r1 = *(const float4*)(base + WW);
        float v0 = fmaxf(fmaxf(r0.x, r0.y), fmaxf(r1.x, r1.y));
        float v1 = fmaxf(fmaxf(r0.z, r0.w), fmaxf(r1.z, r1.w));
        int m = t * (PH * PW) + ph * PW + pw2 * 2;
        *(__nv_bfloat162*)(g_mv + ((size_t)b * CV + c) * MM + m) = __floats2bfloat162_rn(v0, v1);
    } else {
        int i = (blk - 5632) * 256 + threadIdx.x;
        const int per_b = CV * NN / 4;
        int b = i / per_b;
        int r = i - b * per_b;
        ((float4*)out)[(size_t)b * (2 * CV * NN / 4) + r] = ((const float4*)qv)[i];
    }
}

// ---------------- fused attention (R6 structure, verbatim loop) ----------------
// CTA: 64n x 128c, 4 warps (16n x 128c each), m-chunks of 64, no split-K.
// grid (2 c-halves, 64 n, 2 b) = 256 CTAs -> 2 CTAs/SM.
// smem: Qs[64ck][72n] @0 (9216B) | 3 stages: Ks[64m][72ck] (9216) + Vs[128c][72m] (18432)
#define QS_B 9216u
#define STG_B 27648u
#define SMEM_TOTAL (QS_B + 3u * STG_B)   // 92160

__global__ void __launch_bounds__(128, 2) fused_attn_kernel(float* __restrict__ out) {
    extern __shared__ char sm[];
    const uint32_t sb = (uint32_t)__cvta_generic_to_shared(sm);
    const int b = blockIdx.z, n0 = blockIdx.y * 64, c0 = blockIdx.x * 128;
    const int tid = threadIdx.x;

    const __nv_bfloat16* qb = g_qk + (size_t)b * CK * NN;
    const __nv_bfloat16* kb = g_mk + (size_t)b * MM * CK;
    const __nv_bfloat16* vb = g_mv + (size_t)b * CV * MM;

    // Q load: 64 ck-rows x 8 segs of 16B (row pitch 144B)
    #pragma unroll
    for (int i = 0; i < 4; i++) {
        int e = tid + i * 128;
        int row = e >> 3, seg = e & 7;
        cpasync16(sb + (uint32_t)(row * 144 + seg * 16),
                  qb + (size_t)row * NN + n0 + seg * 8);
    }
    asm volatile("cp.async.commit_group;" ::: "memory");

    auto pf = [&](int ch) {
        uint32_t kst = sb + QS_B + (uint32_t)(ch % 3) * STG_B;
        uint32_t vst = kst + 9216u;
        #pragma unroll
        for (int i = 0; i < 4; i++) {          // K: 64 m-rows x 8 segs
            int e = tid + i * 128;
            int row = e >> 3, seg = e & 7;
            cpasync16(kst + (uint32_t)(row * 144 + seg * 16),
                      kb + (size_t)(ch * 64 + row) * CK + seg * 8);
        }
        #pragma unroll
        for (int i = 0; i < 8; i++) {          // V: 128 c-rows x 8 segs
            int e = tid + i * 128;
            int row = e >> 3, seg = e & 7;
            cpasync16(vst + (uint32_t)(row * 144 + seg * 16),
                      vb + (size_t)(c0 + row) * MM + ch * 64 + seg * 8);
        }
        asm volatile("cp.async.commit_group;" ::: "memory");
    };
    pf(0); pf(1);

    const int wid = tid >> 5, lane = tid & 31;
    const int nw = wid * 16;                   // warp's n base (local)
    const int g = lane >> 2, t = lane & 3;
    const int lr = (lane & 7) + ((lane >> 4) << 3);
    const int lh = (lane >> 3) & 1;

    // wait for Q, then preload Q A-fragments (16n x 64k -> 4 frags)
    asm volatile("cp.async.wait_group 2;" ::: "memory");
    __syncthreads();
    uint32_t q[4][4];
    #pragma unroll
    for (int kf = 0; kf < 4; kf++)
        ldsm4t(q[kf], sb + (uint32_t)((kf * 16 + lr) * 144 + (nw + lh * 8) * 2));

    float acc_o[16][4] = {};
    float rs0 = 0.f, rs1 = 0.f;

    const int NCH = MM / 64;
    for (int ch = 0; ch < NCH; ch++) {
        if (ch + 1 < NCH) asm volatile("cp.async.wait_group 1;" ::: "memory");
        else              asm volatile("cp.async.wait_group 0;" ::: "memory");
        __syncthreads();
        if (ch + 2 < NCH) pf(ch + 2);

        uint32_t kst = sb + QS_B + (uint32_t)(ch % 3) * STG_B;
        uint32_t vst = kst + 9216u;

        // ---- S = Q K^T : warp tile 16n x 64m ----
        float acc_s[8][4] = {};
        #pragma unroll
        for (int jj = 0; jj < 4; jj++) {       // m-pairs (16m each)
            #pragma unroll
            for (int kf = 0; kf < 4; kf++) {
                uint32_t r[4];
                ldsm4(r, kst + (uint32_t)((jj * 16 + lr) * 144 + kf * 32 + lh * 16));
                mma_bf16(acc_s[2 * jj],     q[kf], r);
                mma_bf16(acc_s[2 * jj + 1], q[kf], r + 2);
            }
        }

        // ---- exp2 -> P fragments in registers + rowsum ----
        uint32_t p[4][4];
        #pragma unroll
        for (int mk = 0; mk < 4; mk++) {
            float e0 = ex2(acc_s[2 * mk][0] - 6.f);
            float e1 = ex2(acc_s[2 * mk][1] - 6.f);
            float e2 = ex2(acc_s[2 * mk][2] - 6.f);
            float e3 = ex2(acc_s[2 * mk][3] - 6.f);
            float f0 = ex2(acc_s[2 * mk + 1][0] - 6.f);
            float f1 = ex2(acc_s[2 * mk + 1][1] - 6.f);
            float f2 = ex2(acc_s[2 * mk + 1][2] - 6.f);
            float f3 = ex2(acc_s[2 * mk + 1][3] - 6.f);
            rs0 += (e0 + e1) + (f0 + f1);
            rs1 += (e2 + e3) + (f2 + f3);
            p[mk][0] = pack_bf16x2(e0, e1);
            p[mk][1] = pack_bf16x2(e2, e3);
            p[mk][2] = pack_bf16x2(f0, f1);
            p[mk][3] = pack_bf16x2(f2, f3);
        }

        // ---- O += P V^T : warp tile 16n x 128c ----
        #pragma unroll
        for (int jj = 0; jj < 8; jj++) {       // c-pairs (16c each)
            #pragma unroll
            for (int mk = 0; mk < 4; mk++) {
                uint32_t r[4];
                ldsm4(r, vst + (uint32_t)((jj * 16 + lr) * 144 + mk * 32 + lh * 16));
                mma_bf16(acc_o[2 * jj],     p[mk], r);
                mma_bf16(acc_o[2 * jj + 1], p[mk], r + 2);
            }
        }
    }

    // ---- rowsum reduce over t (rows are warp-private) ----
    rs0 += __shfl_xor_sync(0xffffffffu, rs0, 1);
    rs0 += __shfl_xor_sync(0xffffffffu, rs0, 2);
    rs1 += __shfl_xor_sync(0xffffffffu, rs1, 1);
    rs1 += __shfl_xor_sync(0xffffffffu, rs1, 2);
    float inv0 = 1.f / rs0;
    float inv1 = 1.f / rs1;

    // ---- scale + store ----
    int n = n0 + nw + g;
    #pragma unroll
    for (int ct = 0; ct < 16; ct++) {
        int c = c0 + ct * 8 + 2 * t;
        size_t base0 = ((size_t)b * 2 * CV + CV + c) * NN;
        size_t base1 = base0 + NN;
        out[base0 + n]     = acc_o[ct][0] * inv0;
        out[base1 + n]     = acc_o[ct][1] * inv0;
        out[base0 + n + 8] = acc_o[ct][2] * inv1;
        out[base1 + n + 8] = acc_o[ct][3] * inv1;
    }
}

extern "C" void kernel_launch(void* const* d_in, const int* in_sizes, int n_in,
                              void* d_out, int out_size) {
    const float* memory_keys   = (const float*)d_in[0];
    const float* memory_values = (const float*)d_in[1];
    const float* query_key     = (const float*)d_in[2];
    const float* query_value   = (const float*)d_in[3];
    float* out = (float*)d_out;

    cudaFuncSetAttribute(fused_attn_kernel, cudaFuncAttributeMaxDynamicSharedMemorySize,
                         SMEM_TOTAL);

    prep_kernel<<<7680, 256>>>(memory_keys, memory_values, query_key, query_value, out);

    dim3 gf(CV / 128, NN / 64, BB);   // (2, 64, 2) = 256 CTAs
    fused_attn_kernel<<<gf, 128, SMEM_TOTAL>>>(out);
}

// round 17
// speedup vs baseline: 1.3463x; 1.0201x over previous
#include <cuda_runtime.h>
#include <cuda_bf16.h>
#include <cstdint>

#define BB 2
#define TT 4
#define CK 64
#define CV 256
#define HH 64
#define WW 64
#define PH 32
#define PW 32
#define MM 4096
#define NN 4096
#define SCALE2 0.1803368801111204f   // 0.125 * log2(e)

// Scratch (device globals: allocation-free)
__device__ __align__(128) __nv_bfloat16 g_qk[(size_t)BB * CK * NN];   // scaled Q (exp2 domain)
__device__ __align__(128) __nv_bfloat16 g_mk[(size_t)BB * MM * CK];   // pooled K
__device__ __align__(128) __nv_bfloat16 g_mv[(size_t)BB * CV * MM];   // pooled V [b][c][m]

__device__ __forceinline__ void cpasync16(uint32_t saddr, const void* g) {
    asm volatile("cp.async.cg.shared.global [%0], [%1], 16;" :: "r"(saddr), "l"(g));
}
__device__ __forceinline__ void ldsm4(uint32_t* r, uint32_t a) {
    asm volatile("ldmatrix.sync.aligned.m8n8.x4.shared.b16 {%0,%1,%2,%3},[%4];"
                 : "=r"(r[0]), "=r"(r[1]), "=r"(r[2]), "=r"(r[3]) : "r"(a));
}
__device__ __forceinline__ void ldsm4t(uint32_t* r, uint32_t a) {
    asm volatile("ldmatrix.sync.aligned.m8n8.x4.trans.shared.b16 {%0,%1,%2,%3},[%4];"
                 : "=r"(r[0]), "=r"(r[1]), "=r"(r[2]), "=r"(r[3]) : "r"(a));
}
__device__ __forceinline__ void mma_bf16(float* d, const uint32_t* a, const uint32_t* b) {
    asm volatile(
        "mma.sync.aligned.m16n8k16.row.col.f32.bf16.bf16.f32 "
        "{%0,%1,%2,%3},{%4,%5,%6,%7},{%8,%9},{%0,%1,%2,%3};"
        : "+f"(d[0]), "+f"(d[1]), "+f"(d[2]), "+f"(d[3])
        : "r"(a[0]), "r"(a[1]), "r"(a[2]), "r"(a[3]), "r"(b[0]), "r"(b[1]));
}
__device__ __forceinline__ float ex2(float x) {
    float r;
    asm("ex2.approx.f32 %0, %1;" : "=f"(r) : "f"(x));
    return r;
}
__device__ __forceinline__ uint32_t pack_bf16x2(float a, float b) {
    __nv_bfloat162 h = __floats2bfloat162_rn(a, b);
    return *reinterpret_cast<uint32_t*>(&h);
}

// ---------------- fused prep: cvtq + pool_k + pool_v + qv copy (single launch) ----------
__global__ void __launch_bounds__(256) prep_kernel(const float* __restrict__ mk_in,
                                                   const float* __restrict__ mv_in,
                                                   const float* __restrict__ q_in,
                                                   const float* __restrict__ qv,
                                                   float* __restrict__ out) {
    int blk = blockIdx.x;
    if (blk < 512) {
        int i = blk * 256 + threadIdx.x;
        float4 v = ((const float4*)q_in)[i];
        __nv_bfloat162* dst = (__nv_bfloat162*)g_qk;
        dst[2 * i]     = __floats2bfloat162_rn(v.x * SCALE2, v.y * SCALE2);
        dst[2 * i + 1] = __floats2bfloat162_rn(v.z * SCALE2, v.w * SCALE2);
    } else if (blk < 1536) {
        int idx = (blk - 512) * 256 + threadIdx.x;     // [0, 262144)
        int pw2 = idx & 15; int t1 = idx >> 4;
        int ph = t1 & 31;   int t2 = t1 >> 5;
        int ck = t2 & 63;   int t3 = t2 >> 6;
        int t  = t3 & 3;    int b  = t3 >> 2;
        const float* base = mk_in + ((((size_t)(b * TT + t) * CK + ck) * HH + ph * 2) * WW + pw2 * 4);
        float4 r0 = *(const float4*)base;
        float4 r1 = *(const float4*)(base + WW);
        float v0 = fmaxf(fmaxf(r0.x, r0.y), fmaxf(r1.x, r1.y));
        float v1 = fmaxf(fmaxf(r0.z, r0.w), fmaxf(r1.z, r1.w));
        int m = t * (PH * PW) + ph * PW + pw2 * 2;
        g_mk[((size_t)b * MM + m) * CK + ck]     = __float2bfloat16_rn(v0);
        g_mk[((size_t)b * MM + m + 1) * CK + ck] = __float2bfloat16_rn(v1);
    } else if (blk < 5632) {
        int idx = (blk - 1536) * 256 + threadIdx.x;    // [0, 1048576)
        int pw2 = idx & 15; int t1 = idx >> 4;
        int ph = t1 & 31;   int t2 = t1 >> 5;
        int c  = t2 & 255;  int t3 = t2 >> 8;
        int t  = t3 & 3;    int b  = t3 >> 2;
        const float* base = mv_in + ((((size_t)(b * TT + t) * CV + c) * HH + ph * 2) * WW + pw2 * 4);
        float4 r0 = *(const float4*)base;
        float4 r1 = *(const float4*)(base + WW);
        float v0 = fmaxf(fmaxf(r0.x, r0.y), fmaxf(r1.x, r1.y));
        float v1 = fmaxf(fmaxf(r0.z, r0.w), fmaxf(r1.z, r1.w));
        int m = t * (PH * PW) + ph * PW + pw2 * 2;
        *(__nv_bfloat162*)(g_mv + ((size_t)b * CV + c) * MM + m) = __floats2bfloat162_rn(v0, v1);
    } else {
        int i = (blk - 5632) * 256 + threadIdx.x;
        const int per_b = CV * NN / 4;
        int b = i / per_b;
        int r = i - b * per_b;
        ((float4*)out)[(size_t)b * (2 * CV * NN / 4) + r] = ((const float4*)qv)[i];
    }
}

// ---------------- fused attention (R6 tiling, intra-chunk ILP restructure) ----------------
// CTA: 64n x 128c, 4 warps (16n x 128c each), m-chunks of 64 split into two 32-m halves
// with exp(h) overlapped against independent MMA streams. grid (2, 64, 2) = 256 CTAs.
// smem: Qs[64ck][72n] @0 (9216B) | 3 stages: Ks[64m][72ck] (9216) + Vs[128c][72m] (18432)
#define QS_B 9216u
#define STG_B 27648u
#define SMEM_TOTAL (QS_B + 3u * STG_B)   // 92160

__global__ void __launch_bounds__(128, 2) fused_attn_kernel(float* __restrict__ out) {
    extern __shared__ char sm[];
    const uint32_t sb = (uint32_t)__cvta_generic_to_shared(sm);
    const int b = blockIdx.z, n0 = blockIdx.y * 64, c0 = blockIdx.x * 128;
    const int tid = threadIdx.x;

    const __nv_bfloat16* qb = g_qk + (size_t)b * CK * NN;
    const __nv_bfloat16* kb = g_mk + (size_t)b * MM * CK;
    const __nv_bfloat16* vb = g_mv + (size_t)b * CV * MM;

    // Q load: 64 ck-rows x 8 segs of 16B (row pitch 144B)
    #pragma unroll
    for (int i = 0; i < 4; i++) {
        int e = tid + i * 128;
        int row = e >> 3, seg = e & 7;
        cpasync16(sb + (uint32_t)(row * 144 + seg * 16),
                  qb + (size_t)row * NN + n0 + seg * 8);
    }
    asm volatile("cp.async.commit_group;" ::: "memory");

    auto pf = [&](int ch) {
        uint32_t kst = sb + QS_B + (uint32_t)(ch % 3) * STG_B;
        uint32_t vst = kst + 9216u;
        #pragma unroll
        for (int i = 0; i < 4; i++) {          // K: 64 m-rows x 8 segs
            int e = tid + i * 128;
            int row = e >> 3, seg = e & 7;
            cpasync16(kst + (uint32_t)(row * 144 + seg * 16),
                      kb + (size_t)(ch * 64 + row) * CK + seg * 8);
        }
        #pragma unroll
        for (int i = 0; i < 8; i++) {          // V: 128 c-rows x 8 segs
            int e = tid + i * 128;
            int row = e >> 3, seg = e & 7;
            cpasync16(vst + (uint32_t)(row * 144 + seg * 16),
                      vb + (size_t)(c0 + row) * MM + ch * 64 + seg * 8);
        }
        asm volatile("cp.async.commit_group;" ::: "memory");
    };
    pf(0); pf(1);

    const int wid = tid >> 5, lane = tid & 31;
    const int nw = wid * 16;                   // warp's n base (local)
    const int g = lane >> 2, t = lane & 3;
    const int lr = (lane & 7) + ((lane >> 4) << 3);
    const int lh = (lane >> 3) & 1;

    // wait for Q, then preload Q A-fragments (16n x 64k -> 4 frags)
    asm volatile("cp.async.wait_group 2;" ::: "memory");
    __syncthreads();
    uint32_t q[4][4];
    #pragma unroll
    for (int kf = 0; kf < 4; kf++)
        ldsm4t(q[kf], sb + (uint32_t)((kf * 16 + lr) * 144 + (nw + lh * 8) * 2));

    float acc_o[16][4] = {};
    float rs0 = 0.f, rs1 = 0.f;

    const int NCH = MM / 64;
    for (int ch = 0; ch < NCH; ch++) {
        if (ch + 1 < NCH) asm volatile("cp.async.wait_group 1;" ::: "memory");
        else              asm volatile("cp.async.wait_group 0;" ::: "memory");
        __syncthreads();
        if (ch + 2 < NCH) pf(ch + 2);

        uint32_t kst = sb + QS_B + (uint32_t)(ch % 3) * STG_B;
        uint32_t vst = kst + 9216u;

        // ==== S half 0: m 0..31 ====
        float acc_s[4][4] = {};
        #pragma unroll
        for (int jj = 0; jj < 2; jj++)
            #pragma unroll
            for (int kf = 0; kf < 4; kf++) {
                uint32_t r[4];
                ldsm4(r, kst + (uint32_t)((jj * 16 + lr) * 144 + kf * 32 + lh * 16));
                mma_bf16(acc_s[2 * jj],     q[kf], r);
                mma_bf16(acc_s[2 * jj + 1], q[kf], r + 2);
            }

        // ==== exp half 0 -> p0 (MUFU hidden under S half 1 below) ====
        uint32_t p0[2][4];
        #pragma unroll
        for (int mk = 0; mk < 2; mk++) {
            float e0 = ex2(acc_s[2 * mk][0] - 6.f);
            float e1 = ex2(acc_s[2 * mk][1] - 6.f);
            float e2 = ex2(acc_s[2 * mk][2] - 6.f);
            float e3 = ex2(acc_s[2 * mk][3] - 6.f);
            float f0 = ex2(acc_s[2 * mk + 1][0] - 6.f);
            float f1 = ex2(acc_s[2 * mk + 1][1] - 6.f);
            float f2 = ex2(acc_s[2 * mk + 1][2] - 6.f);
            float f3 = ex2(acc_s[2 * mk + 1][3] - 6.f);
            rs0 += (e0 + e1) + (f0 + f1);
            rs1 += (e2 + e3) + (f2 + f3);
            p0[mk][0] = pack_bf16x2(e0, e1);
            p0[mk][1] = pack_bf16x2(e2, e3);
            p0[mk][2] = pack_bf16x2(f0, f1);
            p0[mk][3] = pack_bf16x2(f2, f3);
        }

        // ==== S half 1: m 32..63 (independent of exp half 0) ====
        float acc_t[4][4] = {};
        #pragma unroll
        for (int jj = 0; jj < 2; jj++)
            #pragma unroll
            for (int kf = 0; kf < 4; kf++) {
                uint32_t r[4];
                ldsm4(r, kst + (uint32_t)(((jj + 2) * 16 + lr) * 144 + kf * 32 + lh * 16));
                mma_bf16(acc_t[2 * jj],     q[kf], r);
                mma_bf16(acc_t[2 * jj + 1], q[kf], r + 2);
            }

        // ==== O += P0 V^T (mk 0..1) — covers exp half 1's latency ====
        #pragma unroll
        for (int jj = 0; jj < 8; jj++)
            #pragma unroll
            for (int mk = 0; mk < 2; mk++) {
                uint32_t r[4];
                ldsm4(r, vst + (uint32_t)((jj * 16 + lr) * 144 + mk * 32 + lh * 16));
                mma_bf16(acc_o[2 * jj],     p0[mk], r);
                mma_bf16(acc_o[2 * jj + 1], p0[mk], r + 2);
            }

        // ==== exp half 1 -> p1 ====
        uint32_t p1[2][4];
        #pragma unroll
        for (int mk = 0; mk < 2; mk++) {
            float e0 = ex2(acc_t[2 * mk][0] - 6.f);
            float e1 = ex2(acc_t[2 * mk][1] - 6.f);
            float e2 = ex2(acc_t[2 * mk][2] - 6.f);
            float e3 = ex2(acc_t[2 * mk][3] - 6.f);
            float f0 = ex2(acc_t[2 * mk + 1][0] - 6.f);
            float f1 = ex2(acc_t[2 * mk + 1][1] - 6.f);
            float f2 = ex2(acc_t[2 * mk + 1][2] - 6.f);
            float f3 = ex2(acc_t[2 * mk + 1][3] - 6.f);
            rs0 += (e0 + e1) + (f0 + f1);
            rs1 += (e2 + e3) + (f2 + f3);
            p1[mk][0] = pack_bf16x2(e0, e1);
            p1[mk][1] = pack_bf16x2(e2, e3);
            p1[mk][2] = pack_bf16x2(f0, f1);
            p1[mk][3] = pack_bf16x2(f2, f3);
        }

        // ==== O += P1 V^T (mk 2..3) ====
        #pragma unroll
        for (int jj = 0; jj < 8; jj++)
            #pragma unroll
            for (int mk = 0; mk < 2; mk++) {
                uint32_t r[4];
                ldsm4(r, vst + (uint32_t)((jj * 16 + lr) * 144 + (mk + 2) * 32 + lh * 16));
                mma_bf16(acc_o[2 * jj],     p1[mk], r);
                mma_bf16(acc_o[2 * jj + 1], p1[mk], r + 2);
            }
    }

    // ---- rowsum reduce over t (rows are warp-private) ----
    rs0 += __shfl_xor_sync(0xffffffffu, rs0, 1);
    rs0 += __shfl_xor_sync(0xffffffffu, rs0, 2);
    rs1 += __shfl_xor_sync(0xffffffffu, rs1, 1);
    rs1 += __shfl_xor_sync(0xffffffffu, rs1, 2);
    float inv0 = 1.f / rs0;
    float inv1 = 1.f / rs1;

    // ---- scale + store ----
    int n = n0 + nw + g;
    #pragma unroll
    for (int ct = 0; ct < 16; ct++) {
        int c = c0 + ct * 8 + 2 * t;
        size_t base0 = ((size_t)b * 2 * CV + CV + c) * NN;
        size_t base1 = base0 + NN;
        out[base0 + n]     = acc_o[ct][0] * inv0;
        out[base1 + n]     = acc_o[ct][1] * inv0;
        out[base0 + n + 8] = acc_o[ct][2] * inv1;
        out[base1 + n + 8] = acc_o[ct][3] * inv1;
    }
}

extern "C" void kernel_launch(void* const* d_in, const int* in_sizes, int n_in,
                              void* d_out, int out_size) {
    const float* memory_keys   = (const float*)d_in[0];
    const float* memory_values = (const float*)d_in[1];
    const float* query_key     = (const float*)d_in[2];
    const float* query_value   = (const float*)d_in[3];
    float* out = (float*)d_out;

    cudaFuncSetAttribute(fused_attn_kernel, cudaFuncAttributeMaxDynamicSharedMemorySize,
                         SMEM_TOTAL);

    prep_kernel<<<7680, 256>>>(memory_keys, memory_values, query_key, query_value, out);

    dim3 gf(CV / 128, NN / 64, BB);   // (2, 64, 2) = 256 CTAs
    fused_attn_kernel<<<gf, 128, SMEM_TOTAL>>>(out);
}